// round 1
// baseline (speedup 1.0000x reference)
#include <cuda_runtime.h>
#include <math.h>

// Problem constants (validated against in_sizes at launch)
#define XD 8            // feature dims (XD == ZD == 8)
#define LCH 64          // t-chunk length
#define RPB 256         // rows per block
#define RPW 64          // rows per warp (2 per lane, packed f32x2)
#define NW  4           // warps per block

// Scratch for per-chunk scan summaries U[c][r] (max 32 chunks x 8192 rows)
__device__ float g_U[64 * 8192];

// ---------------- packed fp32x2 helpers (sm_100a) ----------------
static __device__ __forceinline__ float2 ffma2(float2 a, float2 b, float2 c) {
    float2 d;
    asm("{\n\t"
        ".reg .b64 ra, rb, rc, rd;\n\t"
        "mov.b64 ra, {%2, %3};\n\t"
        "mov.b64 rb, {%4, %5};\n\t"
        "mov.b64 rc, {%6, %7};\n\t"
        "fma.rn.f32x2 rd, ra, rb, rc;\n\t"
        "mov.b64 {%0, %1}, rd;\n\t"
        "}"
        : "=f"(d.x), "=f"(d.y)
        : "f"(a.x), "f"(a.y), "f"(b.x), "f"(b.y), "f"(c.x), "f"(c.y));
    return d;
}

static __device__ __forceinline__ float2 fmul2(float2 a, float2 b) {
    float2 d;
    asm("{\n\t"
        ".reg .b64 ra, rb, rd;\n\t"
        "mov.b64 ra, {%2, %3};\n\t"
        "mov.b64 rb, {%4, %5};\n\t"
        "mul.rn.f32x2 rd, ra, rb;\n\t"
        "mov.b64 {%0, %1}, rd;\n\t"
        "}"
        : "=f"(d.x), "=f"(d.y)
        : "f"(a.x), "f"(a.y), "f"(b.x), "f"(b.y));
    return d;
}

static __device__ __forceinline__ float2 fadd2(float2 a, float2 b) {
    float2 d;
    asm("{\n\t"
        ".reg .b64 ra, rb, rd;\n\t"
        "mov.b64 ra, {%2, %3};\n\t"
        "mov.b64 rb, {%4, %5};\n\t"
        "add.rn.f32x2 rd, ra, rb;\n\t"
        "mov.b64 {%0, %1}, rd;\n\t"
        "}"
        : "=f"(d.x), "=f"(d.y)
        : "f"(a.x), "f"(a.y), "f"(b.x), "f"(b.y));
    return d;
}

static __device__ __forceinline__ float2 splat(float v) { return make_float2(v, v); }

static __device__ __forceinline__ float sigmoidf(float x) {
    return 1.0f / (1.0f + expf(-x));
}

// Load coefficient row-pair {rA, rB} packed into float2[8]
static __device__ __forceinline__ void load_pair(const float* __restrict__ base,
                                                 int rA, int rB, float2 o[XD]) {
    const float4 a0 = *(const float4*)(base + rA * XD);
    const float4 a1 = *(const float4*)(base + rA * XD + 4);
    const float4 b0 = *(const float4*)(base + rB * XD);
    const float4 b1 = *(const float4*)(base + rB * XD + 4);
    o[0] = make_float2(a0.x, b0.x); o[1] = make_float2(a0.y, b0.y);
    o[2] = make_float2(a0.z, b0.z); o[3] = make_float2(a0.w, b0.w);
    o[4] = make_float2(a1.x, b1.x); o[5] = make_float2(a1.y, b1.y);
    o[6] = make_float2(a1.z, b1.z); o[7] = make_float2(a1.w, b1.w);
}

// b_t for a row-pair: gamma . Z[t], split into two 4-chains for shorter latency path
static __device__ __forceinline__ float2 compute_b(const float2 ga[XD],
                                                   float4 z0, float4 z1) {
    float2 b0 = fmul2(ga[0], splat(z0.x));
    b0 = ffma2(ga[1], splat(z0.y), b0);
    b0 = ffma2(ga[2], splat(z0.z), b0);
    b0 = ffma2(ga[3], splat(z0.w), b0);
    float2 b1 = fmul2(ga[4], splat(z1.x));
    b1 = ffma2(ga[5], splat(z1.y), b1);
    b1 = ffma2(ga[6], splat(z1.z), b1);
    b1 = ffma2(ga[7], splat(z1.w), b1);
    return fadd2(b0, b1);
}

// ---------------- Kernel 1: per-chunk scan summaries ----------------
// U[c][r] = sum_{s in chunk c} Ghat^{(chunk_end-1-s)} * b_s,  b_s = gamma[r].Z[s]
__global__ __launch_bounds__(128) void dlm_chunk_kernel(
    const float* __restrict__ Z, const float* __restrict__ G,
    const float* __restrict__ gamma, int R, int T)
{
    __shared__ __align__(16) float sZ[LCH * XD];
    const int c = blockIdx.y;
    const int t0 = c * LCH;
    for (int i = threadIdx.x; i < LCH * XD; i += blockDim.x)
        sZ[i] = Z[t0 * XD + i];
    __syncthreads();

    const int warp = threadIdx.x >> 5, lane = threadIdx.x & 31;
    const int rbase = blockIdx.x * RPB + warp * RPW;
    const int rA = rbase + lane, rB = rA + 32;

    float2 ga[XD];
    load_pair(gamma, rA, rB, ga);
    const float2 g2 = make_float2(sigmoidf(G[rA]), sigmoidf(G[rB]));

    float2 u = make_float2(0.f, 0.f);
#pragma unroll 4
    for (int i = 0; i < LCH; ++i) {
        const float4 z0 = *(const float4*)&sZ[i * XD];
        const float4 z1 = *(const float4*)&sZ[i * XD + 4];
        const float2 b = compute_b(ga, z0, z1);
        u = ffma2(g2, u, b);          // u = Ghat*u + b_t
    }
    g_U[c * R + rA] = u.x;
    g_U[c * R + rB] = u.y;
}

// ---------------- Kernel 2: main compute ----------------
// out[r,t] = theta[r,t] + eta[r].X[t] + zeta[r].Z[t]
// theta carry-in for chunk c rebuilt from U via a tiny prefix scan.
__global__ __launch_bounds__(128) void dlm_main_kernel(
    const float* __restrict__ X, const float* __restrict__ Z,
    const float* __restrict__ G, const float* __restrict__ eta,
    const float* __restrict__ zeta, const float* __restrict__ gamma,
    float* __restrict__ out, int R, int T)
{
    __shared__ __align__(16) float sX[LCH * XD];
    __shared__ __align__(16) float sZ[LCH * XD];
    __shared__ float tile[NW][32 * 65];   // [t (stride 65)][row 0..63], conflict-free

    const int c = blockIdx.y;
    const int t0 = c * LCH;
    for (int i = threadIdx.x; i < LCH * XD; i += blockDim.x) {
        sX[i] = X[t0 * XD + i];
        sZ[i] = Z[t0 * XD + i];
    }
    __syncthreads();

    const int warp = threadIdx.x >> 5, lane = threadIdx.x & 31;
    const int rbase = blockIdx.x * RPB + warp * RPW;
    const int rA = rbase + lane, rB = rA + 32;

    float2 et[XD], ze[XD], ga[XD];
    load_pair(eta,   rA, rB, et);
    load_pair(zeta,  rA, rB, ze);
    load_pair(gamma, rA, rB, ga);
    const float2 g2 = make_float2(sigmoidf(G[rA]), sigmoidf(G[rB]));

    // Ghat^LCH via exact repeated squaring (LCH = 64 = 2^6)
    float2 gl = g2;
#pragma unroll
    for (int s = 0; s < 6; ++s) gl = fmul2(gl, gl);

    // Carry-in: theta_{c*L} = scan over previous chunks' U
    float2 th = make_float2(0.f, 0.f);
    for (int j = 0; j < c; ++j) {
        const float2 u = make_float2(__ldg(&g_U[j * R + rA]),
                                     __ldg(&g_U[j * R + rB]));
        th = ffma2(gl, th, u);
    }

    float* mytile = tile[warp];
#pragma unroll
    for (int tb = 0; tb < LCH / 32; ++tb) {
#pragma unroll 4
        for (int i = 0; i < 32; ++i) {
            const int tt = tb * 32 + i;
            const float4 x0 = *(const float4*)&sX[tt * XD];
            const float4 x1 = *(const float4*)&sX[tt * XD + 4];
            const float4 z0 = *(const float4*)&sZ[tt * XD];
            const float4 z1 = *(const float4*)&sZ[tt * XD + 4];

            // out = theta_t + eta.X + zeta.Z  (accumulate straight onto theta)
            float2 acc = th;
            acc = ffma2(et[0], splat(x0.x), acc);
            acc = ffma2(et[1], splat(x0.y), acc);
            acc = ffma2(et[2], splat(x0.z), acc);
            acc = ffma2(et[3], splat(x0.w), acc);
            acc = ffma2(et[4], splat(x1.x), acc);
            acc = ffma2(et[5], splat(x1.y), acc);
            acc = ffma2(et[6], splat(x1.z), acc);
            acc = ffma2(et[7], splat(x1.w), acc);
            acc = ffma2(ze[0], splat(z0.x), acc);
            acc = ffma2(ze[1], splat(z0.y), acc);
            acc = ffma2(ze[2], splat(z0.z), acc);
            acc = ffma2(ze[3], splat(z0.w), acc);
            acc = ffma2(ze[4], splat(z1.x), acc);
            acc = ffma2(ze[5], splat(z1.y), acc);
            acc = ffma2(ze[6], splat(z1.z), acc);
            acc = ffma2(ze[7], splat(z1.w), acc);

            const float2 b = compute_b(ga, z0, z1);
            th = ffma2(g2, th, b);    // theta_{t+1} = Ghat*theta_t + b_t

            mytile[i * 65 + lane]      = acc.x;   // bank (i+lane)%32: conflict-free
            mytile[i * 65 + lane + 32] = acc.y;
        }
        __syncwarp();
        // Coalesced writeback: one 128B row per warp-iteration
        const int tbase = t0 + tb * 32;
#pragma unroll 8
        for (int rr = 0; rr < 64; ++rr) {
            out[(rbase + rr) * T + tbase + lane] = mytile[lane * 65 + rr];
        }
        __syncwarp();
    }
}

// ---------------- launch ----------------
extern "C" void kernel_launch(void* const* d_in, const int* in_sizes, int n_in,
                              void* d_out, int out_size) {
    const float* X     = (const float*)d_in[0];   // [T, 8]
    const float* Z     = (const float*)d_in[1];   // [T, 8]
    const float* G     = (const float*)d_in[2];   // [R]
    const float* eta   = (const float*)d_in[3];   // [R, 8]
    const float* zeta  = (const float*)d_in[4];   // [R, 8]
    const float* gamma = (const float*)d_in[5];   // [R, 8]
    float* out = (float*)d_out;                   // [R, T]

    const int T = in_sizes[0] / XD;   // 2048
    const int R = in_sizes[2];        // 4096

    dim3 block(NW * 32);
    dim3 grid(R / RPB, T / LCH);      // (16, 32) = 512 CTAs

    dlm_chunk_kernel<<<grid, block>>>(Z, G, gamma, R, T);
    dlm_main_kernel<<<grid, block>>>(X, Z, G, eta, zeta, gamma, out, R, T);
}